// round 5
// baseline (speedup 1.0000x reference)
#include <cuda_runtime.h>
#include <cuda_bf16.h>

#define IMG_W 1024
#define IMG_H 1024
#define NC_TOTAL 48
#define ROWS 16           // output rows per CTA
#define STRIPS (IMG_H / ROWS)

typedef unsigned long long ull;

// ---- packed f32x2 helpers (sm_103a; ptxas never auto-generates these) ----
__device__ __forceinline__ ull pack2(float lo, float hi) {
    ull d;
    asm("mov.b64 %0, {%1, %2};" : "=l"(d) : "r"(__float_as_uint(lo)), "r"(__float_as_uint(hi)));
    return d;
}
__device__ __forceinline__ void unpack2(ull v, float& lo, float& hi) {
    unsigned a, b;
    asm("mov.b64 {%0, %1}, %2;" : "=r"(a), "=r"(b) : "l"(v));
    lo = __uint_as_float(a); hi = __uint_as_float(b);
}
__device__ __forceinline__ ull fma2(ull a, ull b, ull c) {
    ull d; asm("fma.rn.f32x2 %0, %1, %2, %3;" : "=l"(d) : "l"(a), "l"(b), "l"(c)); return d;
}
__device__ __forceinline__ ull mul2(ull a, ull b) {
    ull d; asm("mul.rn.f32x2 %0, %1, %2;" : "=l"(d) : "l"(a), "l"(b)); return d;
}
__device__ __forceinline__ ull add2(ull a, ull b) {
    ull d; asm("add.rn.f32x2 %0, %1, %2;" : "=l"(d) : "l"(a), "l"(b)); return d;
}

// One input row held packed: P[k] = {a[k], a[k+1]}, k=0..4 (a[0..5] = halo-extended 6 px)
// s01 = {sum3(p0..p2), sum3(p1..p3)}, s23 = {sum3(p2..p4), sum3(p3..p5)}, p=a*a
struct Row { ull P[5]; ull s01, s23; };

__device__ __forceinline__ float4 loadrow(const float* base, int rr) {
    const int rc = min(IMG_H - 1, max(0, rr));
    return *reinterpret_cast<const float4*>(base + (size_t)rc * IMG_W);
}

__device__ __forceinline__ void finish_row(Row& rw, float4 v, const float* base,
                                           int rr, int lane, int x0) {
    const int rc = min(IMG_H - 1, max(0, rr));
    const float* rp = base + (size_t)rc * IMG_W;
    float a0 = __shfl_up_sync(0xffffffffu, v.w, 1);
    float a5 = __shfl_down_sync(0xffffffffu, v.x, 1);
    if (lane == 0)  a0 = (x0 > 0)           ? __ldg(rp - 1) : 0.f;
    if (lane == 31) a5 = (x0 + 4 < IMG_W)   ? __ldg(rp + 4) : 0.f;

    const float m = (rr == rc) ? 1.f : 0.f;   // zero rows outside the image
    a0 *= m; a5 *= m;
    const float a1 = v.x * m, a2 = v.y * m, a3 = v.z * m, a4 = v.w * m;

    rw.P[0] = pack2(a0, a1);
    rw.P[1] = pack2(a1, a2);
    rw.P[2] = pack2(a2, a3);
    rw.P[3] = pack2(a3, a4);
    rw.P[4] = pack2(a4, a5);

    const ull pp0 = mul2(rw.P[0], rw.P[0]);
    const ull pp1 = mul2(rw.P[1], rw.P[1]);
    const ull pp2 = mul2(rw.P[2], rw.P[2]);
    const ull pp3 = mul2(rw.P[3], rw.P[3]);
    const ull pp4 = mul2(rw.P[4], rw.P[4]);
    rw.s01 = add2(add2(pp0, pp1), pp2);
    rw.s23 = add2(add2(pp2, pp3), pp4);
}

__device__ __forceinline__ float4 compute_out(const Row& A, const Row& B, const Row& C,
                                              const ull* __restrict__ wp) {
    ull n01 = mul2(wp[0], A.P[0]);
    n01 = fma2(wp[1], A.P[1], n01);
    n01 = fma2(wp[2], A.P[2], n01);
    n01 = fma2(wp[3], B.P[0], n01);
    n01 = fma2(wp[4], B.P[1], n01);
    n01 = fma2(wp[5], B.P[2], n01);
    n01 = fma2(wp[6], C.P[0], n01);
    n01 = fma2(wp[7], C.P[1], n01);
    n01 = fma2(wp[8], C.P[2], n01);

    ull n23 = mul2(wp[0], A.P[2]);
    n23 = fma2(wp[1], A.P[3], n23);
    n23 = fma2(wp[2], A.P[4], n23);
    n23 = fma2(wp[3], B.P[2], n23);
    n23 = fma2(wp[4], B.P[3], n23);
    n23 = fma2(wp[5], B.P[4], n23);
    n23 = fma2(wp[6], C.P[2], n23);
    n23 = fma2(wp[7], C.P[3], n23);
    n23 = fma2(wp[8], C.P[4], n23);

    const ull q01 = add2(add2(A.s01, B.s01), C.s01);
    const ull q23 = add2(add2(A.s23, B.s23), C.s23);

    float n0, n1, n2, n3, q0, q1, q2, q3;
    unpack2(n01, n0, n1); unpack2(n23, n2, n3);
    unpack2(q01, q0, q1); unpack2(q23, q2, q3);

    float4 o;
    o.x = n0 * rsqrtf(q0);
    o.y = n1 * rsqrtf(q1);
    o.z = n2 * rsqrtf(q2);
    o.w = n3 * rsqrtf(q3);
    return o;
}

// Sliding-window normalized depthwise 3x3: one CTA = full-width strip of 16 rows.
__global__ void __launch_bounds__(256, 3) normconv3x3_v5(
    const float* __restrict__ x,
    const float* __restrict__ wt,
    float* __restrict__ out)
{
    const int lane = threadIdx.x & 31;
    const int x0 = (int)threadIdx.x << 2;      // 0..1020
    const int b = blockIdx.x;
    const int strip = b & (STRIPS - 1);        // 64 strips
    const int nc = b >> 6;                     // 0..47
    const int c = nc % 3;
    const int y0 = strip * ROWS;

    // normalized, lane-duplicated packed weights
    float w[9];
    float s2 = 0.f;
#pragma unroll
    for (int k = 0; k < 9; k++) { w[k] = __ldg(&wt[c * 9 + k]); s2 += w[k] * w[k]; }
    const float winv = rsqrtf(s2);
    ull wp[9];
#pragma unroll
    for (int k = 0; k < 9; k++) { const float wn = w[k] * winv; wp[k] = pack2(wn, wn); }

    const float* base = x + ((size_t)nc << 20) + x0;
    float* op = out + ((size_t)nc << 20) + (size_t)y0 * IMG_W + x0;

    Row win[3];
    // prologue: rows y0-1 and y0 fully ingested; row y0+1 load in flight
    finish_row(win[0], loadrow(base, y0 - 1), base, y0 - 1, lane, x0);
    finish_row(win[1], loadrow(base, y0),     base, y0,     lane, x0);
    float4 vbuf = loadrow(base, y0 + 1);

#pragma unroll
    for (int r = 0; r < ROWS; r++) {
        finish_row(win[(r + 2) % 3], vbuf, base, y0 + r + 1, lane, x0);
        if (r < ROWS - 1) vbuf = loadrow(base, y0 + r + 2);   // prefetch next row
        const float4 o = compute_out(win[r % 3], win[(r + 1) % 3], win[(r + 2) % 3], wp);
        *reinterpret_cast<float4*>(op + (size_t)r * IMG_W) = o;
    }
}

extern "C" void kernel_launch(void* const* d_in, const int* in_sizes, int n_in,
                              void* d_out, int out_size) {
    const float* x  = (const float*)d_in[0];
    const float* wt = (const float*)d_in[1];
    float* out = (float*)d_out;

    dim3 grid(NC_TOTAL * STRIPS);   // 3072 blocks, 256 threads (full 1024-px row)
    normconv3x3_v5<<<grid, 256>>>(x, wt, out);
}

// round 6
// speedup vs baseline: 1.2237x; 1.2237x over previous
#include <cuda_runtime.h>
#include <cuda_bf16.h>

#define IMG_W 1024
#define IMG_H 1024
#define NC_TOTAL 48

typedef unsigned long long ull;

// ---- packed f32x2 helpers (sm_103a-only; ptxas never auto-fuses) ----
__device__ __forceinline__ ull pack2(float lo, float hi) {
    ull d;
    asm("mov.b64 %0, {%1, %2};" : "=l"(d) : "r"(__float_as_uint(lo)), "r"(__float_as_uint(hi)));
    return d;
}
__device__ __forceinline__ void unpack2(ull v, float& lo, float& hi) {
    unsigned a, b;
    asm("mov.b64 {%0, %1}, %2;" : "=r"(a), "=r"(b) : "l"(v));
    lo = __uint_as_float(a); hi = __uint_as_float(b);
}
__device__ __forceinline__ ull fma2(ull a, ull b, ull c) {
    ull d; asm("fma.rn.f32x2 %0, %1, %2, %3;" : "=l"(d) : "l"(a), "l"(b), "l"(c)); return d;
}
__device__ __forceinline__ ull mul2(ull a, ull b) {
    ull d; asm("mul.rn.f32x2 %0, %1, %2;" : "=l"(d) : "l"(a), "l"(b)); return d;
}
__device__ __forceinline__ ull add2(ull a, ull b) {
    ull d; asm("add.rn.f32x2 %0, %1, %2;" : "=l"(d) : "l"(a), "l"(b)); return d;
}

// v6 = v4 structure (6 front-batched row loads, 4-row tile, early store)
//      + f32x2 packed arithmetic with minimal pack overhead.
__global__ void __launch_bounds__(256, 3) normconv3x3_v6(
    const float* __restrict__ x,
    const float* __restrict__ wt,
    float* __restrict__ out)
{
    const int lane = threadIdx.x & 31;
    const int x0 = (int)threadIdx.x << 2;          // 0..1020
    const int b = blockIdx.x;
    const int y0 = (b & 255) << 2;                 // 4-row tiles
    const int nc = b >> 8;                         // 0..47
    const int c = nc % 3;

    // Normalized per-channel 3x3 weights, lane-duplicated packed
    float w[9];
    float s2 = 0.f;
#pragma unroll
    for (int k = 0; k < 9; k++) { w[k] = __ldg(&wt[c * 9 + k]); s2 += w[k] * w[k]; }
    const float winv = rsqrtf(s2);
    ull wp[9];
#pragma unroll
    for (int k = 0; k < 9; k++) { const float wn = w[k] * winv; wp[k] = pack2(wn, wn); }

    const float* base = x + ((size_t)nc << 20) + x0;

    // ---- Phase 1: 6 branch-free batched row loads (MLP=6) ----
    float4 v[6];
    if (y0 != 0 && y0 != IMG_H - 4) {
#pragma unroll
        for (int r = 0; r < 6; r++)
            v[r] = *reinterpret_cast<const float4*>(base + (size_t)(y0 - 1 + r) * IMG_W);
    } else {
#pragma unroll
        for (int r = 0; r < 6; r++) {
            const int rr = y0 - 1 + r;
            const int rc = min(IMG_H - 1, max(0, rr));
            v[r] = *reinterpret_cast<const float4*>(base + (size_t)rc * IMG_W);
            if (rr != rc) v[r] = make_float4(0.f, 0.f, 0.f, 0.f);
        }
    }

    // ---- Phase 2: batched shuffle halos ----
    float h0[6], h5[6];
#pragma unroll
    for (int r = 0; r < 6; r++) {
        h0[r] = __shfl_up_sync(0xffffffffu, v[r].w, 1);
        h5[r] = __shfl_down_sync(0xffffffffu, v[r].x, 1);
    }
    if (lane == 0) {
#pragma unroll
        for (int r = 0; r < 6; r++) {
            h0[r] = 0.f;
            if (x0 > 0) {
                const int rr = y0 - 1 + r;
                const int rc = min(IMG_H - 1, max(0, rr));
                h0[r] = (rr == rc) ? __ldg(base + (size_t)rc * IMG_W - 1) : 0.f;
            }
        }
    }
    if (lane == 31) {
#pragma unroll
        for (int r = 0; r < 6; r++) {
            h5[r] = 0.f;
            if (x0 + 4 < IMG_W) {
                const int rr = y0 - 1 + r;
                const int rc = min(IMG_H - 1, max(0, rr));
                h5[r] = (rr == rc) ? __ldg(base + (size_t)rc * IMG_W + 4) : 0.f;
            }
        }
    }

    // ---- Phase 3: packed compute, early store ----
    ull n01[4], n23[4], q01[4], q23[4];
    const ull z = pack2(0.f, 0.f);
#pragma unroll
    for (int o = 0; o < 4; o++) { n01[o] = z; n23[o] = z; q01[o] = z; q23[o] = z; }

    float* op = out + ((size_t)nc << 20) + (size_t)y0 * IMG_W + x0;

#pragma unroll
    for (int r = 0; r < 6; r++) {
        // 5 overlapping px-pairs; P1/P3 are the natural float4 halves (free pairs)
        const ull P0 = pack2(h0[r],  v[r].x);
        const ull P1 = pack2(v[r].x, v[r].y);
        const ull P2 = pack2(v[r].y, v[r].z);
        const ull P3 = pack2(v[r].z, v[r].w);
        const ull P4 = pack2(v[r].w, h5[r]);

        // squared-window row sums: s01 = {p0+p1+p2, p1+p2+p3}, s23 likewise
        const ull pp0 = mul2(P0, P0);
        const ull pp1 = mul2(P1, P1);
        const ull pp2 = mul2(P2, P2);
        const ull pp3 = mul2(P3, P3);
        const ull pp4 = mul2(P4, P4);
        const ull s01 = add2(add2(pp0, pp1), pp2);
        const ull s23 = add2(add2(pp2, pp3), pp4);

#pragma unroll
        for (int o = 0; o < 4; o++) {
            const int k = r - o;                    // weight row for this (input,output) pair
            if (k >= 0 && k <= 2) {
                const ull w0 = wp[k * 3 + 0], w1 = wp[k * 3 + 1], w2 = wp[k * 3 + 2];
                n01[o] = fma2(w0, P0, fma2(w1, P1, fma2(w2, P2, n01[o])));
                n23[o] = fma2(w0, P2, fma2(w1, P3, fma2(w2, P4, n23[o])));
                q01[o] = add2(q01[o], s01);
                q23[o] = add2(q23[o], s23);
            }
        }

        // output row (r-2) complete after consuming input row r
        if (r >= 2) {
            const int o = r - 2;
            float nn0, nn1, nn2, nn3, qq0, qq1, qq2, qq3;
            unpack2(n01[o], nn0, nn1); unpack2(n23[o], nn2, nn3);
            unpack2(q01[o], qq0, qq1); unpack2(q23[o], qq2, qq3);
            float4 ov;
            ov.x = nn0 * rsqrtf(qq0);
            ov.y = nn1 * rsqrtf(qq1);
            ov.z = nn2 * rsqrtf(qq2);
            ov.w = nn3 * rsqrtf(qq3);
            *reinterpret_cast<float4*>(op + (size_t)o * IMG_W) = ov;
        }
    }
}

extern "C" void kernel_launch(void* const* d_in, const int* in_sizes, int n_in,
                              void* d_out, int out_size) {
    const float* x  = (const float*)d_in[0];
    const float* wt = (const float*)d_in[1];
    float* out = (float*)d_out;

    dim3 grid(NC_TOTAL * (IMG_H / 4));   // 12288 blocks, 256 threads = full row width
    normconv3x3_v6<<<grid, 256>>>(x, wt, out);
}

// round 7
// speedup vs baseline: 1.5110x; 1.2347x over previous
#include <cuda_runtime.h>
#include <cuda_bf16.h>

#define IMG_W 1024
#define IMG_H 1024
#define NC_TOTAL 48
#define ROWS 8
#define NLOAD (ROWS + 2)

// v7 = v4 structure scaled to 8-row tiles:
//  - 10 front-batched float4 row loads (MLP=10)
//  - read amplification 1.25x (vs 1.5x at 4 rows)
//  - shuffle halo software-pipelined one row ahead
//  - early store: only 3 output rows of accumulators live at once
__global__ void __launch_bounds__(256, 3) normconv3x3_v7(
    const float* __restrict__ x,
    const float* __restrict__ wt,
    float* __restrict__ out)
{
    const int lane = threadIdx.x & 31;
    const int x0 = (int)threadIdx.x << 2;          // 0..1020
    const int b = blockIdx.x;
    const int y0 = (b & 127) << 3;                 // 128 8-row tiles
    const int nc = b >> 7;                         // 0..47
    const int c = nc % 3;

    const float* base = x + ((size_t)nc << 20) + x0;

    // ---- Phase 1: 10 branch-free batched row loads (MLP=10) ----
    float4 v[NLOAD];
    if (y0 != 0 && y0 != IMG_H - ROWS) {
#pragma unroll
        for (int r = 0; r < NLOAD; r++)
            v[r] = *reinterpret_cast<const float4*>(base + (size_t)(y0 - 1 + r) * IMG_W);
    } else {
#pragma unroll
        for (int r = 0; r < NLOAD; r++) {
            const int rr = y0 - 1 + r;
            const int rc = min(IMG_H - 1, max(0, rr));
            v[r] = *reinterpret_cast<const float4*>(base + (size_t)rc * IMG_W);
            if (rr != rc) v[r] = make_float4(0.f, 0.f, 0.f, 0.f);
        }
    }

    // Weights AFTER the bulk loads are in flight (keeps LDG batch tight)
    float w[9];
    float ws2 = 0.f;
#pragma unroll
    for (int k = 0; k < 9; k++) { w[k] = __ldg(&wt[c * 9 + k]); ws2 += w[k] * w[k]; }
    const float winv = rsqrtf(ws2);
#pragma unroll
    for (int k = 0; k < 9; k++) w[k] *= winv;

    float num[ROWS][4], sq[ROWS][4];
    float* op = out + ((size_t)nc << 20) + (size_t)y0 * IMG_W + x0;

    // Prologue halo for row 0 (global row y0-1)
    float h0c = __shfl_up_sync(0xffffffffu, v[0].w, 1);
    float h5c = __shfl_down_sync(0xffffffffu, v[0].x, 1);
    {
        const int rr = y0 - 1;
        if (lane == 0)  h0c = (x0 > 0 && rr >= 0)          ? __ldg(base + (size_t)rr * IMG_W - 1) : 0.f;
        if (lane == 31) h5c = (x0 + 4 < IMG_W && rr >= 0)  ? __ldg(base + (size_t)rr * IMG_W + 4) : 0.f;
    }

#pragma unroll
    for (int r = 0; r < NLOAD; r++) {
        // Pipeline: start next row's halo before computing this row
        float h0n = 0.f, h5n = 0.f;
        if (r + 1 < NLOAD) {
            h0n = __shfl_up_sync(0xffffffffu, v[r + 1].w, 1);
            h5n = __shfl_down_sync(0xffffffffu, v[r + 1].x, 1);
            const int rr = y0 + r;                 // global row of v[r+1]
            if (lane == 0)  h0n = (x0 > 0 && rr < IMG_H)         ? __ldg(base + (size_t)rr * IMG_W - 1) : 0.f;
            if (lane == 31) h5n = (x0 + 4 < IMG_W && rr < IMG_H) ? __ldg(base + (size_t)rr * IMG_W + 4) : 0.f;
        }

        const float a[6] = { h0c, v[r].x, v[r].y, v[r].z, v[r].w, h5c };

        float p[6];
#pragma unroll
        for (int i = 0; i < 6; i++) p[i] = a[i] * a[i];
        const float u = p[1] + p[2];
        const float t = p[3] + p[4];
        const float s[4] = { p[0] + u, u + p[3], p[2] + t, t + p[5] };

#pragma unroll
        for (int o = 0; o < ROWS; o++) {
            const int k = r - o;                    // weight row for this (input,output) pair
            if (k == 0) {
                // first contribution: initialize (no pre-zeroing of accumulators)
#pragma unroll
                for (int j = 0; j < 4; j++) {
                    num[o][j] = fmaf(w[0], a[j], fmaf(w[1], a[j + 1], w[2] * a[j + 2]));
                    sq[o][j] = s[j];
                }
            } else if (k == 1 || k == 2) {
                const float w0 = w[k * 3 + 0], w1 = w[k * 3 + 1], w2 = w[k * 3 + 2];
#pragma unroll
                for (int j = 0; j < 4; j++) {
                    num[o][j] = fmaf(w0, a[j], fmaf(w1, a[j + 1], fmaf(w2, a[j + 2], num[o][j])));
                    sq[o][j] += s[j];
                }
            }
        }

        // output row (r-2) complete after consuming input row r
        if (r >= 2) {
            const int o = r - 2;
            float4 ov;
            ov.x = num[o][0] * rsqrtf(sq[o][0]);
            ov.y = num[o][1] * rsqrtf(sq[o][1]);
            ov.z = num[o][2] * rsqrtf(sq[o][2]);
            ov.w = num[o][3] * rsqrtf(sq[o][3]);
            *reinterpret_cast<float4*>(op + (size_t)o * IMG_W) = ov;
        }

        h0c = h0n; h5c = h5n;
    }
}

extern "C" void kernel_launch(void* const* d_in, const int* in_sizes, int n_in,
                              void* d_out, int out_size) {
    const float* x  = (const float*)d_in[0];
    const float* wt = (const float*)d_in[1];
    float* out = (float*)d_out;

    dim3 grid(NC_TOTAL * (IMG_H / ROWS));   // 6144 blocks, 256 threads = full row width
    normconv3x3_v7<<<grid, 256>>>(x, wt, out);
}